// round 13
// baseline (speedup 1.0000x reference)
#include <cuda_runtime.h>
#include <cuda_bf16.h>

#define JT    128   // j-tile width
#define IT    512   // i-tile height (4 rows per thread)
#define NTHR  128
#define RPT   (IT / NTHR)
#define MAXB  4096

__device__ double        g_partials[MAXB];
__device__ unsigned int  g_ticket = 0;

typedef unsigned long long u64;

__device__ __forceinline__ u64 pack2(float lo, float hi) {
    u64 r; asm("mov.b64 %0, {%1, %2};" : "=l"(r) : "f"(lo), "f"(hi)); return r;
}
__device__ __forceinline__ void unpack2(u64 v, float& lo, float& hi) {
    asm("mov.b64 {%0, %1}, %2;" : "=f"(lo), "=f"(hi) : "l"(v));
}
__device__ __forceinline__ u64 add2(u64 a, u64 b) {
    u64 r; asm("add.rn.f32x2 %0, %1, %2;" : "=l"(r) : "l"(a), "l"(b)); return r;
}

// Exact per-pair loss (general path): t1 = 0.2s - d, t2 = d - s, u = -d.
__device__ __forceinline__ float sel_loss(float t1, float t2, float u) {
    float mm = fmaxf(t1, t2);
    float s  = (u > 0.0f) ? u : mm;
    return fmaxf(s, 0.0f);
}

// Counting step, predicate-free: c = 1.0/0.0; cnt += c; w += cnt. Exact ints in fp32.
__device__ __forceinline__ void cstep(float& cnt, float& w, float pi, float pj) {
    float c;
    asm("set.ge.f32.f32 %0, %1, %2;" : "=f"(c) : "f"(pi), "f"(pj));
    cnt += c;
    w   += cnt;
}

// Band step (exact): acc += max( (pj - pi) + 2*Delta*[pi>=pj], 0 ); twoD += 2.
__device__ __forceinline__ void bstep(float& acc, float& twoD, float pi, float pj) {
    float c;
    asm("set.ge.f32.f32 %0, %1, %2;" : "=f"(c) : "f"(pi), "f"(pj));
    float e = pj - pi;
    float t = fmaf(c, twoD, e);
    acc += fmaxf(t, 0.0f);
    twoD += 2.0f;
}

// Packed full-tile general path for two rows (exact reference op sequence).
__device__ __forceinline__ float hot_rows(const ulonglong2* qxyv, const u64* qzv,
                                          u64 P12a, u64 P12b, u64 NPIa, u64 NPIb) {
    float a0 = 0.f, a1 = 0.f, b0 = 0.f, b1 = 0.f;
    #pragma unroll 8
    for (int k = 0; k < JT / 2; ++k) {
        ulonglong2 ab = qxyv[k];
        u64        zz = qzv[k];
        {
            u64 tA = add2(P12a, ab.x), tB = add2(P12a, ab.y), uu = add2(NPIa, zz);
            float t1, t2, t3, t4, u0, u1;
            unpack2(tA, t1, t2); unpack2(tB, t3, t4); unpack2(uu, u0, u1);
            a0 += sel_loss(t1, t2, u0);
            a1 += sel_loss(t3, t4, u1);
        }
        {
            u64 tA = add2(P12b, ab.x), tB = add2(P12b, ab.y), uu = add2(NPIb, zz);
            float t1, t2, t3, t4, u0, u1;
            unpack2(tA, t1, t2); unpack2(tB, t3, t4); unpack2(uu, u0, u1);
            b0 += sel_loss(t1, t2, u0);
            b1 += sel_loss(t3, t4, u1);
        }
    }
    return (a0 + a1) + (b0 + b1);
}

__device__ __forceinline__ float scal_row(const float* fx, const float* qz,
                                          float pi, float gif, float c02, float step,
                                          int jend) {
    const float P1 = c02 * gif - pi, P2 = pi - step * gif;
    float a = 0.f;
    for (int jj = 0; jj <= jend; ++jj)
        a += sel_loss(P1 + fx[2 * jj], P2 + fx[2 * jj + 1], qz[jj] - pi);
    return a;
}

__global__ void __launch_bounds__(NTHR, 8)
dl_fused_kernel(const float* __restrict__ p,
                const float* __restrict__ z_spacing,
                const float* __restrict__ nth_slice,
                float* __restrict__ out,
                int n, int nblocks) {
    __shared__ __align__(16) u64   qxy64[JT];   // (x_j, y_j) packed (general path)
    __shared__ __align__(8)  float qzf[JT];     // p_j
    __shared__ __align__(16) float sI[IT];      // p_i broadcast (count/band paths)
    __shared__ float  r_max[NTHR / 32], r_min[NTHR / 32];
    __shared__ double wsum[NTHR / 32];
    __shared__ bool   is_last;

    const int tid = threadIdx.x;

    // Heavy-first: highest t (diagonal/general) gets lowest blockIdx.
    int t  = (nblocks - 1) - blockIdx.x;
    // Decode (ti, tj): per-ti count = 4*(ti+1), start(ti) = 2*ti*(ti+1).
    int ti = (int)((sqrtf(2.0f * (float)t + 1.0f) - 1.0f) * 0.5f);
    while (2 * (ti + 1) * (ti + 2) <= t) ti++;
    while (2 * ti * (ti + 1) > t) ti--;
    const int tj = t - 2 * ti * (ti + 1);

    const float step = z_spacing[0] * nth_slice[0];   // == 10 exactly for this data
    const float c02  = 0.2f * step;                   // == 2 exactly

    const int gj0  = tj * JT;
    const int base = ti * IT;

    // Stage j-tile (one j per thread). Lane keeps its own pj in a register.
    float pjreg;
    {
        int j = gj0 + tid;
        pjreg = (j < n) ? p[j] : 0.0f;
        float jf = (float)j;
        qxy64[tid] = pack2(pjreg - c02 * jf, step * jf - pjreg);
        qzf[tid]   = pjreg;
    }

    // Stage i-rows (4 per thread).
    float pis[RPT];
    int   gis[RPT];
    bool  vs[RPT];
    #pragma unroll
    for (int r = 0; r < RPT; ++r) {
        gis[r] = base + r * NTHR + tid;
        vs[r]  = (gis[r] < n);
        pis[r] = vs[r] ? p[gis[r]] : 0.0f;
        sI[r * NTHR + tid] = pis[r];
    }

    // Classification reductions: pImax (i-tile), pJmin (j-tile).
    {
        float lmax = fmaxf(fmaxf(pis[0], pis[1]), fmaxf(pis[2], pis[3]));
        float lmin = pjreg;
        #pragma unroll
        for (int off = 16; off > 0; off >>= 1) {
            lmax = fmaxf(lmax, __shfl_xor_sync(0xffffffffu, lmax, off));
            lmin = fminf(lmin, __shfl_xor_sync(0xffffffffu, lmin, off));
        }
        if ((tid & 31) == 0) { r_max[tid >> 5] = lmax; r_min[tid >> 5] = lmin; }
    }
    __syncthreads();

    const float pImax = fmaxf(fmaxf(r_max[0], r_max[1]), fmaxf(r_max[2], r_max[3]));
    const float pJmin = fminf(fminf(r_min[0], r_min[1]), fminf(r_min[2], r_min[3]));
    const float range = pImax - pJmin;

    const int  dminI   = base - (gj0 + JT - 1);
    const bool fulltls = (base + IT <= n) && (gj0 + JT <= n) && (dminI >= 1) &&
                         (step == 10.0f);
    const bool fastcnt = fulltls && (range < (float)(2 * dminI));
    const bool fastbnd = fulltls && (range <= (float)(10 * dminI));

    double v;

    if (fastcnt) {
        // loss(i,j) = 2*(i-j)*[pi>=pj] - (pi - pj) exactly.
        float c0 = 0.f, w0 = 0.f, c1 = 0.f, w1 = 0.f;
        float c2 = 0.f, w2 = 0.f, c3 = 0.f, w3 = 0.f;
        const float4* sI4 = (const float4*)sI;
        float4 q = sI4[0];
        #pragma unroll 8
        for (int k = 0; k < IT / 4; ++k) {
            float4 qn;
            if (k + 1 < IT / 4) qn = sI4[k + 1];   // prefetch next
            cstep(c0, w0, q.x, pjreg);
            cstep(c1, w1, q.y, pjreg);
            cstep(c2, w2, q.z, pjreg);
            cstep(c3, w3, q.w, pjreg);
            q = qn;
        }
        // m = 4k + r: Sum_m m*c_m = Sum_r [4*(K*cnt_r - w_r) + r*cnt_r], K = IT/4.
        const float CNT = (c0 + c1) + (c2 + c3);
        const float SM  = 4.0f * ((float)(IT / 4) * CNT - ((w0 + w1) + (w2 + w3)))
                        + (c1 + 2.0f * c2 + 3.0f * c3);
        const int   jg  = gj0 + tid;
        const float tpart = (float)(base - jg) * CNT + SM;   // Sum_i (i-j)*[pi>=pj]
        v = 2.0 * (double)tpart
          - (double)JT * (((double)pis[0] + (double)pis[1])
                        + ((double)pis[2] + (double)pis[3]))
          + (double)IT * (double)pjreg;
    } else if (fastbnd) {
        // loss = max((pj-pi) + 2*Delta*[pi>=pj], 0), Delta tracked in register.
        float twoD = 2.0f * (float)(base - (gj0 + tid));
        float a0 = 0.f, a1 = 0.f, a2 = 0.f, a3 = 0.f;
        const float4* sI4 = (const float4*)sI;
        float4 q = sI4[0];
        #pragma unroll 8
        for (int k = 0; k < IT / 4; ++k) {
            float4 qn;
            if (k + 1 < IT / 4) qn = sI4[k + 1];   // prefetch next
            bstep(a0, twoD, q.x, pjreg);
            bstep(a1, twoD, q.y, pjreg);
            bstep(a2, twoD, q.z, pjreg);
            bstep(a3, twoD, q.w, pjreg);
            q = qn;
        }
        v = (double)((a0 + a1) + (a2 + a3));
    } else {
        // General exact path; per-row-pair dispatch (packed hot vs scalar).
        const bool fullj = (gj0 + JT <= n);
        const int  jlim  = fullj ? JT : max(0, n - gj0);
        const ulonglong2* qxyv = (const ulonglong2*)qxy64;
        const u64*        qzv  = (const u64*)qzf;
        const float*      fx   = (const float*)qxy64;

        float acc = 0.f;
        #pragma unroll
        for (int pr = 0; pr < RPT; pr += 2) {
            const int ra = pr, rb = pr + 1;
            if (fullj && vs[rb] && (gis[ra] - gj0) >= JT - 1) {
                const float ga = (float)gis[ra], gb = (float)gis[rb];
                const float pa = pis[ra],        pb = pis[rb];
                acc += hot_rows(qxyv, qzv,
                                pack2(c02 * ga - pa, pa - step * ga),
                                pack2(c02 * gb - pb, pb - step * gb),
                                pack2(-pa, -pa), pack2(-pb, -pb));
            } else {
                #pragma unroll
                for (int r = pr; r < pr + 2; ++r) {
                    const int rel = vs[r] ? (gis[r] - gj0) : -1;
                    if (rel >= 0 && jlim > 0)
                        acc += scal_row(fx, qzf, pis[r], (float)gis[r], c02, step,
                                        min(rel, jlim - 1));
                }
            }
        }
        v = (double)acc;
    }

    // Block reduction in double.
    #pragma unroll
    for (int off = 16; off > 0; off >>= 1)
        v += __shfl_down_sync(0xffffffffu, v, off);
    if ((tid & 31) == 0) wsum[tid >> 5] = v;
    __syncthreads();
    if (tid < 32) {
        v = (tid < (NTHR / 32)) ? wsum[tid] : 0.0;
        #pragma unroll
        for (int off = 2; off > 0; off >>= 1)
            v += __shfl_down_sync(0xffffffffu, v, off);
        if (tid == 0) {
            g_partials[blockIdx.x] = v;
            __threadfence();
            unsigned int ticket = atomicAdd(&g_ticket, 1u);
            is_last = (ticket == (unsigned int)(nblocks - 1));
        }
    }
    __syncthreads();

    // Last block: final reduce, write output, reset ticket.
    if (is_last) {
        __threadfence();
        double s = 0.0;
        for (int i = tid; i < nblocks; i += NTHR)
            s += g_partials[i];
        #pragma unroll
        for (int off = 16; off > 0; off >>= 1)
            s += __shfl_down_sync(0xffffffffu, s, off);
        if ((tid & 31) == 0) wsum[tid >> 5] = s;
        __syncthreads();
        if (tid == 0) {
            double tot = 0.0;
            #pragma unroll
            for (int w = 0; w < NTHR / 32; ++w) tot += wsum[w];
            double nn = (double)n * (double)n;
            out[0] = (float)(tot / nn);
            g_ticket = 0;   // reset for next graph replay
        }
    }
}

extern "C" void kernel_launch(void* const* d_in, const int* in_sizes, int n_in,
                              void* d_out, int out_size) {
    const float* p   = (const float*)d_in[0];
    const float* z   = (const float*)d_in[1];
    const float* nth = (const float*)d_in[2];
    float* out = (float*)d_out;
    int n = in_sizes[0];

    int nti = (n + IT - 1) / IT;
    int nblocks = 2 * nti * (nti + 1);   // n = 8192 -> 544
    if (nblocks > MAXB) nblocks = MAXB;

    dl_fused_kernel<<<nblocks, NTHR>>>(p, z, nth, out, n, nblocks);
}

// round 14
// speedup vs baseline: 1.1380x; 1.1380x over previous
#include <cuda_runtime.h>
#include <cuda_bf16.h>

#define JT    128   // j-tile width
#define IT    256   // i-tile height (2 rows per thread)
#define NTHR  128
#define MAXB  4096

__device__ double        g_partials[MAXB];
__device__ unsigned int  g_ticket = 0;

// Counting step: c = 1.0/0.0 (pred-as-data); cnt += c; w += cnt. Exact ints in fp32.
__device__ __forceinline__ void cstep(float& cnt, float& w, float pi, float pj) {
    float c;
    asm("set.ge.f32.f32 %0, %1, %2;" : "=f"(c) : "f"(pi), "f"(pj));
    cnt += c;
    w   += cnt;
}

// Band step (exact when d <= 10*Delta): val = max(2D*[d>=0] - d, 0).
__device__ __forceinline__ void bstep(float& acc, float& twoD, float pi, float pj) {
    float c;
    asm("set.ge.f32.f32 %0, %1, %2;" : "=f"(c) : "f"(pi), "f"(pj));
    float nd = pj - pi;                 // -d (exact negation)
    float m  = fmaf(c, twoD, nd);       // d>=0: fl(2D-d); d<0: -d
    acc += fmaxf(m, 0.0f);
    twoD += 8.0f;                       // next i for this lane-slot (stride 4 i's)
}

// Universal sub-diagonal step (exact for ANY d, step==10):
// val = max(m, max(fl(-m - 8D), 0)), m = fl(2D*[d>=0] - d).
__device__ __forceinline__ void ustep(float& acc, float& twoD, float& eightD,
                                      float pi, float pj) {
    float c;
    asm("set.ge.f32.f32 %0, %1, %2;" : "=f"(c) : "f"(pi), "f"(pj));
    float nd = pj - pi;
    float m  = fmaf(c, twoD, nd);
    float t  = fmaf(m, -1.0f, -eightD); // fl(d1 - 8D) when d>=2D branch matters
    acc += fmaxf(m, fmaxf(t, 0.0f));
    twoD   += 8.0f;
    eightD += 32.0f;
}

// Legacy exact-within-tolerance scalar row (diagonal/partial tiles, any step).
__device__ __forceinline__ float scal_row(const float* fx, const float* qz,
                                          float pi, float gif, float c02, float step,
                                          int jend) {
    const float P1 = c02 * gif - pi, P2 = pi - step * gif;
    float a = 0.f;
    for (int jj = 0; jj <= jend; ++jj) {
        float t1 = P1 + fx[2 * jj];
        float t2 = P2 + fx[2 * jj + 1];
        float u  = qz[jj] - pi;
        float mm = fmaxf(t1, t2);
        float s  = (u > 0.0f) ? u : mm;
        a += fmaxf(s, 0.0f);
    }
    return a;
}

__global__ void __launch_bounds__(NTHR, 8)
dl_fused_kernel(const float* __restrict__ p,
                const float* __restrict__ z_spacing,
                const float* __restrict__ nth_slice,
                float* __restrict__ out,
                int n, int nblocks) {
    __shared__ __align__(16) float sI[IT];      // p_i broadcast
    __shared__ __align__(16) float fxj[2 * JT]; // (x_j, y_j) interleaved (scalar path)
    __shared__ __align__(8)  float qzf[JT];     // p_j (scalar path)
    __shared__ float  r_max[NTHR / 32], r_min[NTHR / 32];
    __shared__ double wsum[NTHR / 32];
    __shared__ bool   is_last;

    const int tid = threadIdx.x;

    // Heavy-first: highest t (diagonal) gets lowest blockIdx.
    int t  = (nblocks - 1) - blockIdx.x;
    int ti = (int)((sqrtf(4.0f * (float)t + 1.0f) - 1.0f) * 0.5f);
    while ((ti + 1) * (ti + 2) <= t) ti++;
    while (ti * (ti + 1) > t) ti--;
    const int tj = t - ti * (ti + 1);

    const float step = z_spacing[0] * nth_slice[0];   // == 10 exactly for this data
    const float c02  = 0.2f * step;

    const int gj0  = tj * JT;
    const int base = ti * IT;
    const int jg   = gj0 + tid;

    // Stage j-tile (lane owns one j; pj stays in register).
    float pjreg;
    {
        pjreg = (jg < n) ? p[jg] : 0.0f;
        float jf = (float)jg;
        fxj[2 * tid]     = pjreg - c02 * jf;
        fxj[2 * tid + 1] = step * jf - pjreg;
        qzf[tid]         = pjreg;
    }

    const int  gi0 = base + tid, gi1 = gi0 + NTHR;
    const bool v0 = (gi0 < n), v1 = (gi1 < n);
    const float pi0 = v0 ? p[gi0] : 0.0f;
    const float pi1 = v1 ? p[gi1] : 0.0f;
    sI[tid]        = pi0;
    sI[tid + NTHR] = pi1;

    // Classification: pImax (i-tile), pJmin (j-tile).
    {
        float lmax = fmaxf(pi0, pi1);
        float lmin = pjreg;
        #pragma unroll
        for (int off = 16; off > 0; off >>= 1) {
            lmax = fmaxf(lmax, __shfl_xor_sync(0xffffffffu, lmax, off));
            lmin = fminf(lmin, __shfl_xor_sync(0xffffffffu, lmin, off));
        }
        if ((tid & 31) == 0) { r_max[tid >> 5] = lmax; r_min[tid >> 5] = lmin; }
    }
    __syncthreads();

    const float pImax = fmaxf(fmaxf(r_max[0], r_max[1]), fmaxf(r_max[2], r_max[3]));
    const float pJmin = fminf(fminf(r_min[0], r_min[1]), fminf(r_min[2], r_min[3]));
    const float range = pImax - pJmin;

    const int  dminI = base - (gj0 + JT - 1);
    const bool fullt = (base + IT <= n) && (gj0 + JT <= n) && (dminI >= 1) &&
                       (step == 10.0f);

    double v;
    const float4* sI4 = (const float4*)sI;

    if (fullt && range < (float)(2 * dminI)) {
        // Counting: loss = 2*(i-j)*[pi>=pj] - (pi - pj) exactly (d < 2D everywhere).
        float c0 = 0.f, w0 = 0.f, c1 = 0.f, w1 = 0.f;
        float c2 = 0.f, w2 = 0.f, c3 = 0.f, w3 = 0.f;
        #pragma unroll 16
        for (int k = 0; k < IT / 4; ++k) {
            float4 q = sI4[k];
            cstep(c0, w0, q.x, pjreg);
            cstep(c1, w1, q.y, pjreg);
            cstep(c2, w2, q.z, pjreg);
            cstep(c3, w3, q.w, pjreg);
        }
        const float CNT = (c0 + c1) + (c2 + c3);
        const float SM  = 4.0f * ((float)(IT / 4) * CNT - ((w0 + w1) + (w2 + w3)))
                        + (c1 + 2.0f * c2 + 3.0f * c3);
        const float tpart = (float)(base - jg) * CNT + SM;
        v = 2.0 * (double)tpart
          - (double)JT * ((double)pi0 + (double)pi1)
          + (double)IT * (double)pjreg;
    } else if (fullt && range <= (float)(10 * dminI)) {
        // Band: loss = max(2D*[d>=0] - d, 0) exactly (d <= 10D everywhere).
        float d0 = 2.0f * (float)(base - jg);
        float t0 = d0, t1 = d0 + 2.f, t2 = d0 + 4.f, t3 = d0 + 6.f;
        float a0 = 0.f, a1 = 0.f, a2 = 0.f, a3 = 0.f;
        #pragma unroll 16
        for (int k = 0; k < IT / 4; ++k) {
            float4 q = sI4[k];
            bstep(a0, t0, q.x, pjreg);
            bstep(a1, t1, q.y, pjreg);
            bstep(a2, t2, q.z, pjreg);
            bstep(a3, t3, q.w, pjreg);
        }
        v = (double)((a0 + a1) + (a2 + a3));
    } else if (fullt) {
        // Universal sub-diagonal (any d): exact reference semantics.
        float d0 = 2.0f * (float)(base - jg);
        float t0 = d0, t1 = d0 + 2.f, t2 = d0 + 4.f, t3 = d0 + 6.f;
        float e0 = 4.f * t0, e1 = 4.f * t1, e2 = 4.f * t2, e3 = 4.f * t3;
        float a0 = 0.f, a1 = 0.f, a2 = 0.f, a3 = 0.f;
        #pragma unroll 8
        for (int k = 0; k < IT / 4; ++k) {
            float4 q = sI4[k];
            ustep(a0, t0, e0, q.x, pjreg);
            ustep(a1, t1, e1, q.y, pjreg);
            ustep(a2, t2, e2, q.z, pjreg);
            ustep(a3, t3, e3, q.w, pjreg);
        }
        v = (double)((a0 + a1) + (a2 + a3));
    } else {
        // Diagonal / partial tiles: per-row scalar (within-tolerance legacy form).
        const bool fullj = (gj0 + JT <= n);
        const int  jlim  = fullj ? JT : max(0, n - gj0);
        float acc = 0.f;
        const int rel0 = v0 ? (gi0 - gj0) : -1;
        const int rel1 = v1 ? (gi1 - gj0) : -1;
        if (rel0 >= 0 && jlim > 0)
            acc += scal_row(fxj, qzf, pi0, (float)gi0, c02, step,
                            min(rel0, jlim - 1));
        if (rel1 >= 0 && jlim > 0)
            acc += scal_row(fxj, qzf, pi1, (float)gi1, c02, step,
                            min(rel1, jlim - 1));
        v = (double)acc;
    }

    // Block reduction in double.
    #pragma unroll
    for (int off = 16; off > 0; off >>= 1)
        v += __shfl_down_sync(0xffffffffu, v, off);
    if ((tid & 31) == 0) wsum[tid >> 5] = v;
    __syncthreads();
    if (tid < 32) {
        v = (tid < (NTHR / 32)) ? wsum[tid] : 0.0;
        #pragma unroll
        for (int off = 2; off > 0; off >>= 1)
            v += __shfl_down_sync(0xffffffffu, v, off);
        if (tid == 0) {
            g_partials[blockIdx.x] = v;
            __threadfence();
            unsigned int ticket = atomicAdd(&g_ticket, 1u);
            is_last = (ticket == (unsigned int)(nblocks - 1));
        }
    }
    __syncthreads();

    // Last block: final reduce, write output, reset ticket.
    if (is_last) {
        __threadfence();
        double s = 0.0;
        for (int i = tid; i < nblocks; i += NTHR)
            s += g_partials[i];
        #pragma unroll
        for (int off = 16; off > 0; off >>= 1)
            s += __shfl_down_sync(0xffffffffu, s, off);
        if ((tid & 31) == 0) wsum[tid >> 5] = s;
        __syncthreads();
        if (tid == 0) {
            double tot = 0.0;
            #pragma unroll
            for (int w = 0; w < NTHR / 32; ++w) tot += wsum[w];
            double nn = (double)n * (double)n;
            out[0] = (float)(tot / nn);
            g_ticket = 0;   // reset for next graph replay
        }
    }
}

extern "C" void kernel_launch(void* const* d_in, const int* in_sizes, int n_in,
                              void* d_out, int out_size) {
    const float* p   = (const float*)d_in[0];
    const float* z   = (const float*)d_in[1];
    const float* nth = (const float*)d_in[2];
    float* out = (float*)d_out;
    int n = in_sizes[0];

    int nti = (n + IT - 1) / IT;
    int nblocks = nti * (nti + 1);   // n = 8192 -> 1056
    if (nblocks > MAXB) nblocks = MAXB;

    dl_fused_kernel<<<nblocks, NTHR>>>(p, z, nth, out, n, nblocks);
}

// round 15
// speedup vs baseline: 1.1577x; 1.0173x over previous
#include <cuda_runtime.h>
#include <cuda_bf16.h>

#define JT    128   // j-tile width
#define IT    256   // i-tile height (2 rows per thread)
#define NTHR  128
#define MAXB  4096
#define GRPSH 5                      // 32 blocks per completion group
#define MAXG  ((MAXB >> GRPSH) + 1)

__device__ double        g_partials[MAXB];
__device__ unsigned int  g_gtick[MAXG];   // zero-initialized; reset by group-last
__device__ unsigned int  g_ticket = 0;

// Counting step: c = 1.0/0.0 (pred-as-data); cnt += c; w += cnt. Exact ints in fp32.
__device__ __forceinline__ void cstep(float& cnt, float& w, float pi, float pj) {
    float c;
    asm("set.ge.f32.f32 %0, %1, %2;" : "=f"(c) : "f"(pi), "f"(pj));
    cnt += c;
    w   += cnt;
}

// Band step (exact when d <= 10*Delta): val = max(2D*[d>=0] - d, 0).
__device__ __forceinline__ void bstep(float& acc, float& twoD, float pi, float pj) {
    float c;
    asm("set.ge.f32.f32 %0, %1, %2;" : "=f"(c) : "f"(pi), "f"(pj));
    float nd = pj - pi;
    float m  = fmaf(c, twoD, nd);
    acc += fmaxf(m, 0.0f);
    twoD += 8.0f;
}

// Universal sub-diagonal step (exact for ANY d, step==10):
// val = max(m, max(fl(-m - 8D), 0)), m = fl(2D*[d>=0] - d).
__device__ __forceinline__ void ustep(float& acc, float& twoD, float& eightD,
                                      float pi, float pj) {
    float c;
    asm("set.ge.f32.f32 %0, %1, %2;" : "=f"(c) : "f"(pi), "f"(pj));
    float nd = pj - pi;
    float m  = fmaf(c, twoD, nd);
    float t  = fmaf(m, -1.0f, -eightD);
    acc += fmaxf(m, fmaxf(t, 0.0f));
    twoD   += 8.0f;
    eightD += 32.0f;
}

// Legacy exact scalar row (diagonal/partial tiles, any step).
__device__ __forceinline__ float scal_row(const float* fx, const float* qz,
                                          float pi, float gif, float c02, float step,
                                          int jend) {
    const float P1 = c02 * gif - pi, P2 = pi - step * gif;
    float a = 0.f;
    for (int jj = 0; jj <= jend; ++jj) {
        float t1 = P1 + fx[2 * jj];
        float t2 = P2 + fx[2 * jj + 1];
        float u  = qz[jj] - pi;
        float mm = fmaxf(t1, t2);
        float s  = (u > 0.0f) ? u : mm;
        a += fmaxf(s, 0.0f);
    }
    return a;
}

__global__ void __launch_bounds__(NTHR, 8)
dl_fused_kernel(const float* __restrict__ p,
                const float* __restrict__ z_spacing,
                const float* __restrict__ nth_slice,
                float* __restrict__ out,
                int n, int nblocks) {
    __shared__ __align__(16) float sI[IT];
    __shared__ __align__(16) float fxj[2 * JT];
    __shared__ __align__(8)  float qzf[JT];
    __shared__ float  r_max[NTHR / 32], r_min[NTHR / 32];
    __shared__ double wsum[NTHR / 32];
    __shared__ bool   is_last;

    const int tid = threadIdx.x;

    // Heavy-first: highest t (diagonal) gets lowest blockIdx.
    int t  = (nblocks - 1) - blockIdx.x;
    int ti = (int)((sqrtf(4.0f * (float)t + 1.0f) - 1.0f) * 0.5f);
    while ((ti + 1) * (ti + 2) <= t) ti++;
    while (ti * (ti + 1) > t) ti--;
    const int tj = t - ti * (ti + 1);

    const float step = z_spacing[0] * nth_slice[0];   // == 10 exactly for this data
    const float c02  = 0.2f * step;

    const int gj0  = tj * JT;
    const int base = ti * IT;
    const int jg   = gj0 + tid;

    // Stage j-tile (lane owns one j; pj stays in register).
    float pjreg;
    {
        pjreg = (jg < n) ? p[jg] : 0.0f;
        float jf = (float)jg;
        fxj[2 * tid]     = pjreg - c02 * jf;
        fxj[2 * tid + 1] = step * jf - pjreg;
        qzf[tid]         = pjreg;
    }

    const int  gi0 = base + tid, gi1 = gi0 + NTHR;
    const bool v0 = (gi0 < n), v1 = (gi1 < n);
    const float pi0 = v0 ? p[gi0] : 0.0f;
    const float pi1 = v1 ? p[gi1] : 0.0f;
    sI[tid]        = pi0;
    sI[tid + NTHR] = pi1;

    // Classification: pImax (i-tile), pJmin (j-tile).
    {
        float lmax = fmaxf(pi0, pi1);
        float lmin = pjreg;
        #pragma unroll
        for (int off = 16; off > 0; off >>= 1) {
            lmax = fmaxf(lmax, __shfl_xor_sync(0xffffffffu, lmax, off));
            lmin = fminf(lmin, __shfl_xor_sync(0xffffffffu, lmin, off));
        }
        if ((tid & 31) == 0) { r_max[tid >> 5] = lmax; r_min[tid >> 5] = lmin; }
    }
    __syncthreads();

    const float pImax = fmaxf(fmaxf(r_max[0], r_max[1]), fmaxf(r_max[2], r_max[3]));
    const float pJmin = fminf(fminf(r_min[0], r_min[1]), fminf(r_min[2], r_min[3]));
    const float range = pImax - pJmin;

    const int  dminI = base - (gj0 + JT - 1);
    const bool fullt = (base + IT <= n) && (gj0 + JT <= n) && (dminI >= 1) &&
                       (step == 10.0f);

    double v;
    const float4* sI4 = (const float4*)sI;

    if (fullt && range < (float)(2 * dminI)) {
        // Counting: loss = 2*(i-j)*[pi>=pj] - (pi - pj) exactly (d < 2D everywhere).
        float c0 = 0.f, w0 = 0.f, c1 = 0.f, w1 = 0.f;
        float c2 = 0.f, w2 = 0.f, c3 = 0.f, w3 = 0.f;
        #pragma unroll 16
        for (int k = 0; k < IT / 4; ++k) {
            float4 q = sI4[k];
            cstep(c0, w0, q.x, pjreg);
            cstep(c1, w1, q.y, pjreg);
            cstep(c2, w2, q.z, pjreg);
            cstep(c3, w3, q.w, pjreg);
        }
        const float CNT = (c0 + c1) + (c2 + c3);
        const float SM  = 4.0f * ((float)(IT / 4) * CNT - ((w0 + w1) + (w2 + w3)))
                        + (c1 + 2.0f * c2 + 3.0f * c3);
        const float tpart = (float)(base - jg) * CNT + SM;
        v = 2.0 * (double)tpart
          - (double)JT * ((double)pi0 + (double)pi1)
          + (double)IT * (double)pjreg;
    } else if (fullt && range <= (float)(10 * dminI)) {
        // Band: loss = max(2D*[d>=0] - d, 0) exactly (d <= 10D everywhere).
        float d0 = 2.0f * (float)(base - jg);
        float t0 = d0, t1 = d0 + 2.f, t2 = d0 + 4.f, t3 = d0 + 6.f;
        float a0 = 0.f, a1 = 0.f, a2 = 0.f, a3 = 0.f;
        #pragma unroll 16
        for (int k = 0; k < IT / 4; ++k) {
            float4 q = sI4[k];
            bstep(a0, t0, q.x, pjreg);
            bstep(a1, t1, q.y, pjreg);
            bstep(a2, t2, q.z, pjreg);
            bstep(a3, t3, q.w, pjreg);
        }
        v = (double)((a0 + a1) + (a2 + a3));
    } else if (fullt) {
        // Universal sub-diagonal (any d): exact reference semantics.
        float d0 = 2.0f * (float)(base - jg);
        float t0 = d0, t1 = d0 + 2.f, t2 = d0 + 4.f, t3 = d0 + 6.f;
        float e0 = 4.f * t0, e1 = 4.f * t1, e2 = 4.f * t2, e3 = 4.f * t3;
        float a0 = 0.f, a1 = 0.f, a2 = 0.f, a3 = 0.f;
        #pragma unroll 8
        for (int k = 0; k < IT / 4; ++k) {
            float4 q = sI4[k];
            ustep(a0, t0, e0, q.x, pjreg);
            ustep(a1, t1, e1, q.y, pjreg);
            ustep(a2, t2, e2, q.z, pjreg);
            ustep(a3, t3, e3, q.w, pjreg);
        }
        v = (double)((a0 + a1) + (a2 + a3));
    } else {
        // Diagonal / partial tiles: per-row scalar.
        const bool fullj = (gj0 + JT <= n);
        const int  jlim  = fullj ? JT : max(0, n - gj0);
        float acc = 0.f;
        const int rel0 = v0 ? (gi0 - gj0) : -1;
        const int rel1 = v1 ? (gi1 - gj0) : -1;
        if (rel0 >= 0 && jlim > 0)
            acc += scal_row(fxj, qzf, pi0, (float)gi0, c02, step,
                            min(rel0, jlim - 1));
        if (rel1 >= 0 && jlim > 0)
            acc += scal_row(fxj, qzf, pi1, (float)gi1, c02, step,
                            min(rel1, jlim - 1));
        v = (double)acc;
    }

    // Block reduction in double.
    #pragma unroll
    for (int off = 16; off > 0; off >>= 1)
        v += __shfl_down_sync(0xffffffffu, v, off);
    if ((tid & 31) == 0) wsum[tid >> 5] = v;
    __syncthreads();
    if (tid < 32) {
        v = (tid < (NTHR / 32)) ? wsum[tid] : 0.0;
        #pragma unroll
        for (int off = 2; off > 0; off >>= 1)
            v += __shfl_down_sync(0xffffffffu, v, off);
        if (tid == 0) {
            g_partials[blockIdx.x] = v;
            __threadfence();
            // Two-level completion: per-group counter first (<=32 contenders,
            // distinct addresses), then global counter (<=ngroups contenders).
            const int grp     = (int)blockIdx.x >> GRPSH;
            const int ngroups = (nblocks + (1 << GRPSH) - 1) >> GRPSH;
            const int gcnt    = min(1 << GRPSH, nblocks - (grp << GRPSH));
            bool last = false;
            unsigned g1 = atomicAdd(&g_gtick[grp], 1u);
            if (g1 == (unsigned)(gcnt - 1)) {
                g_gtick[grp] = 0;   // reset for next graph replay
                __threadfence();
                unsigned g2 = atomicAdd(&g_ticket, 1u);
                last = (g2 == (unsigned)(ngroups - 1));
            }
            is_last = last;
        }
    }
    __syncthreads();

    // Last block: final reduce, write output, reset ticket.
    if (is_last) {
        __threadfence();
        double s = 0.0;
        for (int i = tid; i < nblocks; i += NTHR)
            s += g_partials[i];
        #pragma unroll
        for (int off = 16; off > 0; off >>= 1)
            s += __shfl_down_sync(0xffffffffu, s, off);
        if ((tid & 31) == 0) wsum[tid >> 5] = s;
        __syncthreads();
        if (tid == 0) {
            double tot = 0.0;
            #pragma unroll
            for (int w = 0; w < NTHR / 32; ++w) tot += wsum[w];
            double nn = (double)n * (double)n;
            out[0] = (float)(tot / nn);
            g_ticket = 0;   // reset for next graph replay
        }
    }
}

extern "C" void kernel_launch(void* const* d_in, const int* in_sizes, int n_in,
                              void* d_out, int out_size) {
    const float* p   = (const float*)d_in[0];
    const float* z   = (const float*)d_in[1];
    const float* nth = (const float*)d_in[2];
    float* out = (float*)d_out;
    int n = in_sizes[0];

    int nti = (n + IT - 1) / IT;
    int nblocks = nti * (nti + 1);   // n = 8192 -> 1056
    if (nblocks > MAXB) nblocks = MAXB;

    dl_fused_kernel<<<nblocks, NTHR>>>(p, z, nth, out, n, nblocks);
}